// round 1
// baseline (speedup 1.0000x reference)
#include <cuda_runtime.h>

// out[b,e,t] = v2[t]*x[b,e,t] + bias[t] + P[t]
// P[t] = sum_{s<t} x[b,e,s]*v[s]*d^(t-s)   (decayed prefix scan along S)
// d = clip(decay_value[1], 0.9, 1.0)

#define SEQ 2048
#define CHUNK 8
#define THREADS 256   // 256 * 8 = 2048 = SEQ

__global__ void __launch_bounds__(THREADS)
decay_scan_kernel(const float* __restrict__ x,
                  const float* __restrict__ w,      // (S,)
                  const float* __restrict__ v2,     // (S,) diag
                  const float* __restrict__ bias,   // (S,)
                  const float* __restrict__ decay,  // (2,)
                  float* __restrict__ out)
{
    const int tid  = threadIdx.x;
    const int lane = tid & 31;
    const int warp = tid >> 5;
    const long long base = (long long)blockIdx.x * SEQ + tid * CHUNK;
    const int sbase = tid * CHUNK;

    const float d = fminf(fmaxf(decay[1], 0.9f), 1.0f);

    // ---- load 8 x-values and 8 weights (vectorized, coalesced) ----
    float4 x0 = *reinterpret_cast<const float4*>(x + base);
    float4 x1 = *reinterpret_cast<const float4*>(x + base + 4);
    float4 w0 = *reinterpret_cast<const float4*>(w + sbase);
    float4 w1 = *reinterpret_cast<const float4*>(w + sbase + 4);

    float xv[CHUNK] = {x0.x, x0.y, x0.z, x0.w, x1.x, x1.y, x1.z, x1.w};
    float wv[CHUNK] = {w0.x, w0.y, w0.z, w0.w, w1.x, w1.y, w1.z, w1.w};
    float yv[CHUNK];
#pragma unroll
    for (int j = 0; j < CHUNK; j++) yv[j] = xv[j] * wv[j];

    // ---- per-chunk affine transform of the carry: C_out = M*C_in + A ----
    // A = sum_j y[j] * d^(CHUNK-j)   computed by A = d*(A + y[j])
    float A = 0.f;
#pragma unroll
    for (int j = 0; j < CHUNK; j++) A = d * (A + yv[j]);
    float M = d * d;  M = M * M;  M = M * M;   // d^8

    // ---- warp inclusive scan of (A, M) ----
    // combine prev (ap,mp) then cur (A,M): A' = A + M*ap ; M' = M*mp
    float Ai = A, Mi = M;
#pragma unroll
    for (int off = 1; off < 32; off <<= 1) {
        float ap = __shfl_up_sync(0xffffffffu, Ai, off);
        float mp = __shfl_up_sync(0xffffffffu, Mi, off);
        if (lane >= off) { Ai = Ai + Mi * ap; Mi = Mi * mp; }
    }

    // ---- cross-warp combine (8 warps, scalar carry since row carry = 0) ----
    __shared__ float sA[THREADS / 32];
    __shared__ float sM[THREADS / 32];
    if (lane == 31) { sA[warp] = Ai; sM[warp] = Mi; }
    __syncthreads();

    float Cw = 0.f;                       // carry entering this warp
#pragma unroll
    for (int wi = 0; wi < THREADS / 32; wi++) {
        if (wi < warp) Cw = sM[wi] * Cw + sA[wi];
    }

    // exclusive-within-warp transform (lanes 0..lane-1)
    float Ae = __shfl_up_sync(0xffffffffu, Ai, 1);
    float Me = __shfl_up_sync(0xffffffffu, Mi, 1);
    if (lane == 0) { Ae = 0.f; Me = 1.f; }

    float C = Me * Cw + Ae;               // carry entering this thread's chunk = P[sbase]

    // ---- epilogue: out[t] = v2[t]*x[t] + bias[t] + P[t] ----
    float4 v20 = *reinterpret_cast<const float4*>(v2 + sbase);
    float4 v21 = *reinterpret_cast<const float4*>(v2 + sbase + 4);
    float4 b0  = *reinterpret_cast<const float4*>(bias + sbase);
    float4 b1  = *reinterpret_cast<const float4*>(bias + sbase + 4);
    float vv[CHUNK] = {v20.x, v20.y, v20.z, v20.w, v21.x, v21.y, v21.z, v21.w};
    float bv[CHUNK] = {b0.x, b0.y, b0.z, b0.w, b1.x, b1.y, b1.z, b1.w};

    float ov[CHUNK];
#pragma unroll
    for (int j = 0; j < CHUNK; j++) {
        ov[j] = fmaf(vv[j], xv[j], C + bv[j]);
        C = d * (C + yv[j]);
    }

    float4 o0 = {ov[0], ov[1], ov[2], ov[3]};
    float4 o1 = {ov[4], ov[5], ov[6], ov[7]};
    *reinterpret_cast<float4*>(out + base)     = o0;
    *reinterpret_cast<float4*>(out + base + 4) = o1;
}

extern "C" void kernel_launch(void* const* d_in, const int* in_sizes, int n_in,
                              void* d_out, int out_size)
{
    const float* x     = (const float*)d_in[0];  // (B, E, S)
    const float* w     = (const float*)d_in[1];  // (1, S)
    const float* v2    = (const float*)d_in[2];  // (1, S)
    const float* bias  = (const float*)d_in[3];  // (S,)
    const float* decay = (const float*)d_in[4];  // (2, 1)
    float* out = (float*)d_out;

    const int rows = in_sizes[0] / SEQ;          // B * E
    decay_scan_kernel<<<rows, THREADS>>>(x, w, v2, bias, decay, out);
}

// round 2
// speedup vs baseline: 1.1842x; 1.1842x over previous
#include <cuda_runtime.h>

// out[b,e,t] = v2[t]*x[b,e,t] + bias[t] + P[t]
// P[t] = sum_{s<t} x[b,e,s]*w[s]*d^(t-s),  d = clip(decay[1], 0.9, 1.0)
//
// Decayed prefix scan along S. Key structure: the per-chunk decay multiplier is
// the uniform constant d^CHUNK, so every multiplier in the Kogge-Stone scan is
// analytically known — only the additive part A needs shuffling.

#define SEQ 2048
#define CHUNK 8
#define THREADS 256          // 256 * 8 = 2048 = SEQ
#define RPB 8                // rows per block (params register-cached across rows)

__global__ void __launch_bounds__(THREADS)
decay_scan_kernel(const float* __restrict__ x,
                  const float* __restrict__ w,
                  const float* __restrict__ v2,
                  const float* __restrict__ bias,
                  const float* __restrict__ decay,
                  float* __restrict__ out,
                  int rows)
{
    const int tid   = threadIdx.x;
    const int lane  = tid & 31;
    const int warp  = tid >> 5;
    const int sbase = tid * CHUNK;

    const float d = fminf(fmaxf(decay[1], 0.9f), 1.0f);

    // Precomputed decay powers (all scan multipliers are data-independent).
    float d8 = d * d; d8 = d8 * d8; d8 = d8 * d8;          // d^8
    const float m1 = d8;                                    // step off=1 : d^8
    const float m2 = m1 * m1;                               // off=2      : d^16
    const float m4 = m2 * m2;                               // off=4      : d^32
    const float m8 = m4 * m4;                               // off=8      : d^64
    const float m16 = m8 * m8;                              // off=16     : d^128
    const float d256 = m16 * m16;                           // cross-warp : d^256
    // exclusive per-lane multiplier d^(8*lane)
    const float Me = exp2f(8.0f * (float)lane * __log2f(d));

    // ---- register-cache params for this thread's chunk ----
    float4 w0  = *reinterpret_cast<const float4*>(w    + sbase);
    float4 w1  = *reinterpret_cast<const float4*>(w    + sbase + 4);
    float4 v20 = *reinterpret_cast<const float4*>(v2   + sbase);
    float4 v21 = *reinterpret_cast<const float4*>(v2   + sbase + 4);
    float4 b0  = *reinterpret_cast<const float4*>(bias + sbase);
    float4 b1  = *reinterpret_cast<const float4*>(bias + sbase + 4);
    float wv[CHUNK] = {w0.x, w0.y, w0.z, w0.w, w1.x, w1.y, w1.z, w1.w};
    float vv[CHUNK] = {v20.x, v20.y, v20.z, v20.w, v21.x, v21.y, v21.z, v21.w};
    float bv[CHUNK] = {b0.x, b0.y, b0.z, b0.w, b1.x, b1.y, b1.z, b1.w};

    __shared__ float sA[2][THREADS / 32];

    const int row0 = blockIdx.x * RPB;

    // prefetch first row
    float4 xa0, xa1;
    {
        const float* xp = x + (long long)row0 * SEQ + sbase;
        xa0 = *reinterpret_cast<const float4*>(xp);
        xa1 = *reinterpret_cast<const float4*>(xp + 4);
    }

#pragma unroll 1
    for (int r = 0; r < RPB; r++) {
        const int row = row0 + r;
        if (row >= rows) break;   // uniform per block

        // prefetch next row while we scan this one
        float4 xb0, xb1;
        const bool more = (r + 1 < RPB) && (row + 1 < rows);
        if (more) {
            const float* xn = x + (long long)(row + 1) * SEQ + sbase;
            xb0 = *reinterpret_cast<const float4*>(xn);
            xb1 = *reinterpret_cast<const float4*>(xn + 4);
        }

        float xv[CHUNK] = {xa0.x, xa0.y, xa0.z, xa0.w, xa1.x, xa1.y, xa1.z, xa1.w};

        // per-chunk additive term: A = sum_j x[j]*w[j]*d^(CHUNK-j)
        float A = 0.f;
#pragma unroll
        for (int j = 0; j < CHUNK; j++) A = d * fmaf(xv[j], wv[j], A);

        // Kogge-Stone scan of A only (multipliers are precomputed powers of d)
        float Ai = A;
        {
            float ap;
            ap = __shfl_up_sync(0xffffffffu, Ai, 1);  if (lane >= 1)  Ai = fmaf(m1,  ap, Ai);
            ap = __shfl_up_sync(0xffffffffu, Ai, 2);  if (lane >= 2)  Ai = fmaf(m2,  ap, Ai);
            ap = __shfl_up_sync(0xffffffffu, Ai, 4);  if (lane >= 4)  Ai = fmaf(m4,  ap, Ai);
            ap = __shfl_up_sync(0xffffffffu, Ai, 8);  if (lane >= 8)  Ai = fmaf(m8,  ap, Ai);
            ap = __shfl_up_sync(0xffffffffu, Ai, 16); if (lane >= 16) Ai = fmaf(m16, ap, Ai);
        }

        const int p = r & 1;
        if (lane == 31) sA[p][warp] = Ai;
        __syncthreads();

        // cross-warp carry (multiplier is the uniform constant d^256)
        float Cw = 0.f;
#pragma unroll
        for (int wi = 0; wi < THREADS / 32; wi++)
            if (wi < warp) Cw = fmaf(d256, Cw, sA[p][wi]);

        // exclusive additive within warp
        float Ae = __shfl_up_sync(0xffffffffu, Ai, 1);
        if (lane == 0) Ae = 0.f;

        float C = fmaf(Me, Cw, Ae);     // P at start of this thread's chunk

        // epilogue: out[t] = v2[t]*x[t] + bias[t] + P[t]
        float ov[CHUNK];
#pragma unroll
        for (int j = 0; j < CHUNK; j++) {
            ov[j] = fmaf(vv[j], xv[j], C + bv[j]);
            C = d * fmaf(xv[j], wv[j], C);
        }

        float* op = out + (long long)row * SEQ + sbase;
        *reinterpret_cast<float4*>(op)     = make_float4(ov[0], ov[1], ov[2], ov[3]);
        *reinterpret_cast<float4*>(op + 4) = make_float4(ov[4], ov[5], ov[6], ov[7]);

        xa0 = xb0; xa1 = xb1;
    }
}

extern "C" void kernel_launch(void* const* d_in, const int* in_sizes, int n_in,
                              void* d_out, int out_size)
{
    const float* x     = (const float*)d_in[0];  // (B, E, S)
    const float* w     = (const float*)d_in[1];  // (1, S)
    const float* v2    = (const float*)d_in[2];  // (1, S)
    const float* bias  = (const float*)d_in[3];  // (S,)
    const float* decay = (const float*)d_in[4];  // (2, 1)
    float* out = (float*)d_out;

    const int rows   = in_sizes[0] / SEQ;        // B * E
    const int blocks = (rows + RPB - 1) / RPB;
    decay_scan_kernel<<<blocks, THREADS>>>(x, w, v2, bias, decay, out, rows);
}